// round 1
// baseline (speedup 1.0000x reference)
#include <cuda_runtime.h>

#define BB 4
#define CC 84
#define CP 80          // channels participating in the max (points[:, :-4])
#define HH 512
#define WW 512
#define HW (HH * WW)   // 262144
#define HW4 (HW / 4)   // 65536 float4 per plane

// Scratch (allocation-free): probs and mask, 4 MB each.
__device__ float g_probs[BB * HW];
__device__ float g_mask[BB * HW];

// ---------------------------------------------------------------------------
// Pass 1: probs[b,h,w] = max_{c<80} points[b,c,h,w]   (float4 vectorized)
// grid: (HW4/256, 1, BB), block 256
// ---------------------------------------------------------------------------
__global__ void __launch_bounds__(256) max_kernel(const float4* __restrict__ pts) {
    int pix = blockIdx.x * 256 + threadIdx.x;      // 0..HW4-1
    int b   = blockIdx.z;
    const float4* base = pts + (size_t)b * CC * HW4 + pix;

    float4 m = base[0];
    #pragma unroll 5
    for (int c = 1; c < CP; ++c) {
        float4 v = base[(size_t)c * HW4];
        m.x = fmaxf(m.x, v.x);
        m.y = fmaxf(m.y, v.y);
        m.z = fmaxf(m.z, v.z);
        m.w = fmaxf(m.w, v.w);
    }
    reinterpret_cast<float4*>(g_probs)[(size_t)b * HW4 + pix] = m;
}

// ---------------------------------------------------------------------------
// Pass 2: 3x3 NMS mask. Zero-padded borders.
// idx < center (4): strict >   — offsets (-1,-1),(-1,0),(-1,1),(0,-1)
// idx > center    : >=         — offsets (0,1),(1,-1),(1,0),(1,1)
// grid: (HW/256, 1, BB), block 256. Entirely L2-resident (8 MB).
// ---------------------------------------------------------------------------
__device__ __forceinline__ float nb_at(const float* __restrict__ p,
                                       int h, int w) {
    if (h < 0 || h >= HH || w < 0 || w >= WW) return 0.0f;
    return p[h * WW + w];
}

__global__ void __launch_bounds__(256) mask_kernel() {
    int p  = blockIdx.x * 256 + threadIdx.x;       // 0..HW-1
    int b  = blockIdx.z;
    int h  = p >> 9;                               // /512
    int w  = p & (WW - 1);

    const float* probs = g_probs + (size_t)b * HW;
    float c = probs[p];

    bool ok = (c >  nb_at(probs, h - 1, w - 1)) &
              (c >  nb_at(probs, h - 1, w    )) &
              (c >  nb_at(probs, h - 1, w + 1)) &
              (c >  nb_at(probs, h,     w - 1)) &
              (c >= nb_at(probs, h,     w + 1)) &
              (c >= nb_at(probs, h + 1, w - 1)) &
              (c >= nb_at(probs, h + 1, w    )) &
              (c >= nb_at(probs, h + 1, w + 1));

    g_mask[(size_t)b * HW + p] = ok ? 1.0f : 0.0f;
}

// ---------------------------------------------------------------------------
// Pass 3: out = points * mask[pixel]   (float4 vectorized; mask reused from L2)
// grid: (HW4/256, CC, BB), block 256
// ---------------------------------------------------------------------------
__global__ void __launch_bounds__(256) apply_kernel(const float4* __restrict__ pts,
                                                    float4* __restrict__ out) {
    int pix = blockIdx.x * 256 + threadIdx.x;      // 0..HW4-1
    int c   = blockIdx.y;
    int b   = blockIdx.z;

    size_t idx = ((size_t)b * CC + c) * HW4 + pix;
    float4 m = reinterpret_cast<const float4*>(g_mask)[(size_t)b * HW4 + pix];
    float4 v = pts[idx];
    v.x *= m.x;
    v.y *= m.y;
    v.z *= m.z;
    v.w *= m.w;
    out[idx] = v;
}

// ---------------------------------------------------------------------------
extern "C" void kernel_launch(void* const* d_in, const int* in_sizes, int n_in,
                              void* d_out, int out_size) {
    const float4* pts = (const float4*)d_in[0];
    float4*       out = (float4*)d_out;

    dim3 blk(256);
    dim3 g1(HW4 / 256, 1, BB);
    dim3 g2(HW  / 256, 1, BB);
    dim3 g3(HW4 / 256, CC, BB);

    max_kernel  <<<g1, blk>>>(pts);
    mask_kernel <<<g2, blk>>>();
    apply_kernel<<<g3, blk>>>(pts, out);
}